// round 3
// baseline (speedup 1.0000x reference)
#include <cuda_runtime.h>
#include <cuda_bf16.h>
#include <cstdint>
#include <cstddef>

// LSTM: N=32, T=2048, D=H=512, fp32.
// Kernel A (k_inproj): xh[t][g][n] = x[n,t,:]@W_ih[g,:] + b_ih[g] + b_hh[g]  (f32x2 SGEMM)
// Kernel B (k_lstm): persistent 128-CTA recurrence; CTA owns 4 hidden units
//   (16 gate rows). W_hh dup-packed f32x2 in smem; h packed-transposed [j][npair]
//   ULL, global double-buffered; one global barrier per step.

#define TT 2048
#define NB 32
#define DD 512
#define HH 512
#define GG 2048
#define GRID_B 128

typedef unsigned long long ULL;

__device__ float g_xh[(size_t)TT * GG * NB];   // [t][g][n]
__device__ ULL   g_hp[2][HH][NB / 2];          // packed h pairs [buf][j][np]
__device__ int   g_bar[TT];

// ---------- f32x2 helpers ----------
__device__ __forceinline__ ULL f2_dup(float w) {
    ULL d; asm("mov.b64 %0, {%1, %1};" : "=l"(d) : "f"(w)); return d;
}
__device__ __forceinline__ ULL f2_pack(float a, float b) {
    ULL d; asm("mov.b64 %0, {%1, %2};" : "=l"(d) : "f"(a), "f"(b)); return d;
}
__device__ __forceinline__ void ffma2(ULL& c, ULL a, ULL b) {
    asm("fma.rn.f32x2 %0, %1, %2, %0;" : "+l"(c) : "l"(a), "l"(b));
}
__device__ __forceinline__ void fadd2(ULL& a, ULL b) {
    asm("add.rn.f32x2 %0, %0, %1;" : "+l"(a) : "l"(b));
}
__device__ __forceinline__ float2 f2_unpack(ULL v) {
    float2 r; asm("mov.b64 {%0, %1}, %2;" : "=f"(r.x), "=f"(r.y) : "l"(v)); return r;
}
__device__ __forceinline__ int ld_cg_i32(const int* p) {
    int v; asm volatile("ld.global.cg.b32 %0, [%1];" : "=r"(v) : "l"(p)); return v;
}
__device__ __forceinline__ ulonglong2 ldg_cg2(const ULL* p) {
    ulonglong2 v;
    asm volatile("ld.global.cg.v2.u64 {%0, %1}, [%2];" : "=l"(v.x), "=l"(v.y) : "l"(p));
    return v;
}
__device__ __forceinline__ float sig_(float x) { return 1.0f / (1.0f + __expf(-x)); }

// =====================================================================
// init: zero per-step barrier counters and h buffer 0 (h_{-1} = 0)
// =====================================================================
__global__ void k_init() {
    int gid = blockIdx.x * blockDim.x + threadIdx.x;  // 32*256 = 8192
    if (gid < TT) g_bar[gid] = 0;
    if (gid < HH * (NB / 2)) ((ULL*)g_hp)[gid] = 0ULL;  // g_hp[0]
}

// =====================================================================
// Kernel A: input projection. grid (GG/256, TT), 256 threads.
// Thread computes 8 g x 4 n outputs with f32x2 pairs along n.
// =====================================================================
__global__ void k_inproj(const float* __restrict__ x, const float* __restrict__ W,
                         const float* __restrict__ bih, const float* __restrict__ bhh) {
    __shared__ ULL   Wd[16][256];  // [k][g] duplicated pairs, 32KB
    __shared__ float Xs[16][32];   // [k][n], 2KB

    const int t   = blockIdx.y;
    const int g0  = blockIdx.x * 256;
    const int tid = threadIdx.x;
    const int gy  = tid >> 3;  // 0..31, g = g0 + gy*8 + gi
    const int nx  = tid & 7;   // n = nx*4 .. +3

    ULL acc[8][2];
    #pragma unroll
    for (int gi = 0; gi < 8; gi++) {
        int g = g0 + gy * 8 + gi;
        float b = __ldg(bih + g) + __ldg(bhh + g);
        acc[gi][0] = f2_dup(b);
        acc[gi][1] = f2_dup(b);
    }

    const float* wrow = W + (size_t)(g0 + tid) * DD;       // this thread stages g=g0+tid
    const float* xrow = x + ((size_t)(tid >> 2) * TT + t) * DD + (tid & 3) * 4;

    for (int kc = 0; kc < DD; kc += 16) {
        __syncthreads();
        // stage W chunk (duplicated)
        #pragma unroll
        for (int q = 0; q < 4; q++) {
            float4 w4 = *(const float4*)(wrow + kc + q * 4);
            Wd[q * 4 + 0][tid] = f2_dup(w4.x);
            Wd[q * 4 + 1][tid] = f2_dup(w4.y);
            Wd[q * 4 + 2][tid] = f2_dup(w4.z);
            Wd[q * 4 + 3][tid] = f2_dup(w4.w);
        }
        // stage x chunk
        if (tid < 128) {
            int n = tid >> 2, q = tid & 3;
            float4 v = *(const float4*)(xrow + kc);
            Xs[q * 4 + 0][n] = v.x;
            Xs[q * 4 + 1][n] = v.y;
            Xs[q * 4 + 2][n] = v.z;
            Xs[q * 4 + 3][n] = v.w;
        }
        __syncthreads();

        #pragma unroll
        for (int k = 0; k < 16; k++) {
            float4 xv = *(const float4*)&Xs[k][nx * 4];
            ULL xp0 = f2_pack(xv.x, xv.y);
            ULL xp1 = f2_pack(xv.z, xv.w);
            const ulonglong2* wp = (const ulonglong2*)&Wd[k][gy * 8];
            #pragma unroll
            for (int j = 0; j < 4; j++) {
                ulonglong2 ww = wp[j];
                ffma2(acc[j * 2 + 0][0], ww.x, xp0);
                ffma2(acc[j * 2 + 0][1], ww.x, xp1);
                ffma2(acc[j * 2 + 1][0], ww.y, xp0);
                ffma2(acc[j * 2 + 1][1], ww.y, xp1);
            }
        }
    }

    // store [t][g][n]
    #pragma unroll
    for (int gi = 0; gi < 8; gi++) {
        int g = g0 + gy * 8 + gi;
        float2 p0 = f2_unpack(acc[gi][0]);
        float2 p1 = f2_unpack(acc[gi][1]);
        float4 o = make_float4(p0.x, p0.y, p1.x, p1.y);
        *(float4*)(g_xh + ((size_t)t * GG + g) * NB + nx * 4) = o;
    }
}

// =====================================================================
// Kernel B: recurrence. 128 CTAs x 256 threads, persistent.
// smem (ULL units): hs[512*16]      @ 0      (65536 B)  h packed [j][np]
//                   Wd[16*513]      @ 8192   (65664 B)  W_hh dup'd, padded
//                   red[8*16*17]    @ 16400  (17408 B)  partials, padded
//                   vsm[16*17]      @ 18576  (2176 B)   v exchange
// =====================================================================
__global__ void __launch_bounds__(256, 1) k_lstm(const float* __restrict__ Whh,
                                                 float* __restrict__ out) {
    extern __shared__ ULL sm[];
    ULL* hs  = sm;           // [j][np]  j<512, np<16
    ULL* Wd  = sm + 8192;    // [r][j] stride 513
    ULL* red = sm + 16400;   // [jslg][r][np] stride r:17
    ULL* vsm = sm + 18576;   // [r][np] stride 17

    const int tid = threadIdx.x;
    const int cta = blockIdx.x;

    // ---- stage W_hh (dup'd) once: 16 rows x 512 ----
    for (int i = 0; i < 32; i++) {
        int lin = tid + 256 * i;           // 0..8191
        int r = lin >> 9, j = lin & 511;
        int grow = (r >> 2) * HH + cta * 4 + (r & 3);
        Wd[r * 513 + j] = f2_dup(__ldg(Whh + (size_t)grow * HH + j));
    }

    // GEMM-phase mapping
    const int rowg = tid & 7;          // 8 row-groups (2 rows each)
    const int npg  = (tid >> 3) & 3;   // 4 np-groups (4 pairs each)
    const int jslg = tid >> 5;         // 8 j-slices (64 j' each)
    const int r0   = rowg * 2;
    const int np0  = npg * 4;
    const int jb   = jslg * 64;

    // reduce/gate-phase mapping
    const int rr  = tid >> 4;          // 0..15
    const int rnp = tid & 15;          // 0..15
    const int rgrow = (rr >> 2) * HH + cta * 4 + (rr & 3);

    const int gu = tid >> 4;           // gate threads: tid<64 -> u = gu (0..3)
    float c0 = 0.0f, c1 = 0.0f;        // cell state for (u, 2*rnp), (u, 2*rnp+1)

    for (int t = 0; t < TT; t++) {
        // ---- barrier: wait for h_{t-1} from all CTAs ----
        if (t > 0) {
            if (tid == 0) {
                while (ld_cg_i32(&g_bar[t - 1]) < GRID_B) { __nanosleep(32); }
                __threadfence();
            }
        }
        __syncthreads();

        // ---- load global packed h -> smem (coalesced, L2 path) ----
        {
            const ULL* src = &g_hp[t & 1][0][0];
            #pragma unroll
            for (int i = 0; i < 16; i++) {
                int idx = (tid + 256 * i) * 2;       // ULL index, 16B aligned
                ulonglong2 v = ldg_cg2(src + idx);
                *(ulonglong2*)(hs + idx) = v;
            }
        }
        // prefetch xh pair for reduce phase (hide DRAM latency under GEMM)
        ULL xh_pair = *(const ULL*)(g_xh + ((size_t)t * GG + rgrow) * NB + 2 * rnp);
        __syncthreads();

        // ---- GEMM: 2 rows x 4 np x 64 j' per thread ----
        ULL acc[8];
        #pragma unroll
        for (int i = 0; i < 8; i++) acc[i] = 0ULL;
        {
            const ULL* wr0 = Wd + r0 * 513 + jb;
            const ULL* wr1 = wr0 + 513;
            const ULL* hp  = hs + jb * 16 + np0;
            #pragma unroll 4
            for (int j = 0; j < 64; j++) {
                ULL w0 = wr0[j];
                ULL w1 = wr1[j];
                ulonglong2 ha = *(const ulonglong2*)(hp + j * 16);
                ulonglong2 hb = *(const ulonglong2*)(hp + j * 16 + 2);
                ffma2(acc[0], w0, ha.x); ffma2(acc[1], w0, ha.y);
                ffma2(acc[2], w0, hb.x); ffma2(acc[3], w0, hb.y);
                ffma2(acc[4], w1, ha.x); ffma2(acc[5], w1, ha.y);
                ffma2(acc[6], w1, hb.x); ffma2(acc[7], w1, hb.y);
            }
        }
        // write partials
        #pragma unroll
        for (int i = 0; i < 2; i++)
            #pragma unroll
            for (int p = 0; p < 4; p++)
                red[(jslg * 16 + r0 + i) * 17 + np0 + p] = acc[i * 4 + p];
        __syncthreads();

        // ---- reduce 8 slices + xh -> v ----
        {
            ULL s = red[(0 * 16 + rr) * 17 + rnp];
            #pragma unroll
            for (int sl = 1; sl < 8; sl++) fadd2(s, red[(sl * 16 + rr) * 17 + rnp]);
            fadd2(s, xh_pair);
            vsm[rr * 17 + rnp] = s;
        }
        __syncthreads();

        // ---- gates (64 threads: 4 units x 16 np) ----
        if (tid < 64) {
            float2 vi = f2_unpack(vsm[(0 + gu) * 17 + rnp]);
            float2 vf = f2_unpack(vsm[(4 + gu) * 17 + rnp]);
            float2 vo = f2_unpack(vsm[(8 + gu) * 17 + rnp]);
            float2 vg = f2_unpack(vsm[(12 + gu) * 17 + rnp]);
            float i0 = sig_(vi.x), i1 = sig_(vi.y);
            float f0 = sig_(vf.x), f1 = sig_(vf.y);
            float o0 = sig_(vo.x), o1 = sig_(vo.y);
            float gg0 = tanhf(vg.x), gg1 = tanhf(vg.y);
            c0 = f0 * c0 + i0 * gg0;
            c1 = f1 * c1 + i1 * gg1;
            float h0 = o0 * tanhf(c0);
            float h1 = o1 * tanhf(c1);
            int j = cta * 4 + gu;
            g_hp[(t + 1) & 1][j][rnp] = f2_pack(h0, h1);
            out[((size_t)(2 * rnp) * TT + t) * HH + j]     = h0;
            out[((size_t)(2 * rnp + 1) * TT + t) * HH + j] = h1;
            __threadfence();
        }
        __syncthreads();
        if (tid == 0) atomicAdd(&g_bar[t], 1);
    }
}

// =====================================================================
extern "C" void kernel_launch(void* const* d_in, const int* in_sizes, int n_in,
                              void* d_out, int out_size) {
    const float* x   = (const float*)d_in[0];
    const float* Wih = (const float*)d_in[1];
    const float* bih = (const float*)d_in[2];
    const float* Whh = (const float*)d_in[3];
    const float* bhh = (const float*)d_in[4];
    float* out = (float*)d_out;

    k_init<<<32, 256>>>();

    dim3 gA(GG / 256, TT);
    k_inproj<<<gA, 256>>>(x, Wih, bih, bhh);

    const int smemB = 18848 * 8;  // 150784 B
    cudaFuncSetAttribute(k_lstm, cudaFuncAttributeMaxDynamicSharedMemorySize, smemB);
    k_lstm<<<GRID_B, 256, smemB>>>(Whh, out);
}

// round 4
// speedup vs baseline: 1.0286x; 1.0286x over previous
#include <cuda_runtime.h>
#include <cuda_bf16.h>
#include <cstdint>
#include <cstddef>

// LSTM: N=32, T=2048, D=H=512, fp32.
// Kernel A (k_inproj): xh[t][g][n] = x[n,t,:]@W_ih[g,:] + b_ih[g] + b_hh[g]  (f32x2 SGEMM)
// Kernel B (k_lstm): persistent 128-CTA recurrence; CTA owns 4 hidden units
//   (16 gate rows). W_hh dup-packed f32x2 in smem. h exchange via global
//   double buffer + per-step release/acquire flags. Per-warp pipelined
//   h-slice fill fused into the GEMM (each warp owns a 64-row j-slice).

#define TT 2048
#define NB 32
#define DD 512
#define HH 512
#define GG 2048
#define GRID_B 128

typedef unsigned long long ULL;

__device__ float g_xh[(size_t)TT * GG * NB];   // [t][g][n]
__device__ ULL   g_hp[2][HH][NB / 2];          // packed h pairs [buf][j][np]
__device__ int   g_bar[TT];

// ---------- f32x2 / memory helpers ----------
__device__ __forceinline__ ULL f2_dup(float w) {
    ULL d; asm("mov.b64 %0, {%1, %1};" : "=l"(d) : "f"(w)); return d;
}
__device__ __forceinline__ ULL f2_pack(float a, float b) {
    ULL d; asm("mov.b64 %0, {%1, %2};" : "=l"(d) : "f"(a), "f"(b)); return d;
}
__device__ __forceinline__ void ffma2(ULL& c, ULL a, ULL b) {
    asm("fma.rn.f32x2 %0, %1, %2, %0;" : "+l"(c) : "l"(a), "l"(b));
}
__device__ __forceinline__ void fadd2(ULL& a, ULL b) {
    asm("add.rn.f32x2 %0, %0, %1;" : "+l"(a) : "l"(b));
}
__device__ __forceinline__ float2 f2_unpack(ULL v) {
    float2 r; asm("mov.b64 {%0, %1}, %2;" : "=f"(r.x), "=f"(r.y) : "l"(v)); return r;
}
__device__ __forceinline__ int ld_acq(const int* p) {
    int v; asm volatile("ld.acquire.gpu.global.b32 %0, [%1];" : "=r"(v) : "l"(p)); return v;
}
__device__ __forceinline__ void red_release(int* p) {
    asm volatile("red.release.gpu.global.add.s32 [%0], 1;" :: "l"(p));
}
__device__ __forceinline__ ulonglong2 ldg_cg2(const ULL* p) {
    ulonglong2 v;
    asm volatile("ld.global.cg.v2.u64 {%0, %1}, [%2];" : "=l"(v.x), "=l"(v.y) : "l"(p));
    return v;
}
__device__ __forceinline__ void stg_cg64(ULL* p, ULL v) {
    asm volatile("st.global.cg.u64 [%0], %1;" :: "l"(p), "l"(v));
}
// fast sigmoid / tanh via ex2.approx + rcp.approx (err ~1e-6, budget 1e-3)
__device__ __forceinline__ float sig_(float x) {
    float e, r;
    asm("ex2.approx.f32 %0, %1;" : "=f"(e) : "f"(-1.442695041f * x));
    asm("rcp.approx.f32 %0, %1;" : "=f"(r) : "f"(e + 1.0f));
    return r;
}
__device__ __forceinline__ float tanh_(float x) {
    float e, r;
    asm("ex2.approx.f32 %0, %1;" : "=f"(e) : "f"(2.885390082f * x));
    asm("rcp.approx.f32 %0, %1;" : "=f"(r) : "f"(e + 1.0f));
    return fmaf(-2.0f, r, 1.0f);
}

// =====================================================================
// init: zero per-step flags and h buffer 0 (h_{-1} = 0)
// =====================================================================
__global__ void k_init() {
    int gid = blockIdx.x * blockDim.x + threadIdx.x;  // 8192
    if (gid < TT) g_bar[gid] = 0;
    if (gid < HH * (NB / 2)) ((ULL*)g_hp)[gid] = 0ULL;  // g_hp[0]
}

// =====================================================================
// Kernel A: input projection. grid (GG/256, TT), 256 threads.
// Thread computes 8 g x 4 n outputs with f32x2 pairs along n.
// =====================================================================
__global__ void k_inproj(const float* __restrict__ x, const float* __restrict__ W,
                         const float* __restrict__ bih, const float* __restrict__ bhh) {
    __shared__ ULL   Wd[16][256];  // [k][g] duplicated pairs
    __shared__ float Xs[16][32];   // [k][n]

    const int t   = blockIdx.y;
    const int g0  = blockIdx.x * 256;
    const int tid = threadIdx.x;
    const int gy  = tid >> 3;  // 0..31
    const int nx  = tid & 7;   // n block

    ULL acc[8][2];
    #pragma unroll
    for (int gi = 0; gi < 8; gi++) {
        int g = g0 + gy * 8 + gi;
        float b = __ldg(bih + g) + __ldg(bhh + g);
        acc[gi][0] = f2_dup(b);
        acc[gi][1] = f2_dup(b);
    }

    const float* wrow = W + (size_t)(g0 + tid) * DD;
    const float* xrow = x + ((size_t)(tid >> 2) * TT + t) * DD + (tid & 3) * 4;

    for (int kc = 0; kc < DD; kc += 16) {
        __syncthreads();
        #pragma unroll
        for (int q = 0; q < 4; q++) {
            float4 w4 = *(const float4*)(wrow + kc + q * 4);
            Wd[q * 4 + 0][tid] = f2_dup(w4.x);
            Wd[q * 4 + 1][tid] = f2_dup(w4.y);
            Wd[q * 4 + 2][tid] = f2_dup(w4.z);
            Wd[q * 4 + 3][tid] = f2_dup(w4.w);
        }
        if (tid < 128) {
            int n = tid >> 2, q = tid & 3;
            float4 v = *(const float4*)(xrow + kc);
            Xs[q * 4 + 0][n] = v.x;
            Xs[q * 4 + 1][n] = v.y;
            Xs[q * 4 + 2][n] = v.z;
            Xs[q * 4 + 3][n] = v.w;
        }
        __syncthreads();

        #pragma unroll
        for (int k = 0; k < 16; k++) {
            float4 xv = *(const float4*)&Xs[k][nx * 4];
            ULL xp0 = f2_pack(xv.x, xv.y);
            ULL xp1 = f2_pack(xv.z, xv.w);
            const ulonglong2* wp = (const ulonglong2*)&Wd[k][gy * 8];
            #pragma unroll
            for (int j = 0; j < 4; j++) {
                ulonglong2 ww = wp[j];
                ffma2(acc[j * 2 + 0][0], ww.x, xp0);
                ffma2(acc[j * 2 + 0][1], ww.x, xp1);
                ffma2(acc[j * 2 + 1][0], ww.y, xp0);
                ffma2(acc[j * 2 + 1][1], ww.y, xp1);
            }
        }
    }

    #pragma unroll
    for (int gi = 0; gi < 8; gi++) {
        int g = g0 + gy * 8 + gi;
        float2 p0 = f2_unpack(acc[gi][0]);
        float2 p1 = f2_unpack(acc[gi][1]);
        float4 o = make_float4(p0.x, p0.y, p1.x, p1.y);
        *(float4*)(g_xh + ((size_t)t * GG + g) * NB + nx * 4) = o;
    }
}

// =====================================================================
// Kernel B: recurrence. 128 CTAs x 256 threads, persistent.
// smem (ULL): hs[8192] @0, Wd[16*513] @8192, red[8*16*17] @16400, vsm[16*17] @18576
// =====================================================================
__global__ void __launch_bounds__(256, 1) k_lstm(const float* __restrict__ Whh,
                                                 float* __restrict__ out) {
    extern __shared__ ULL sm[];
    ULL* hs  = sm;           // [j][np]  j<512, np<16 (flat j*16+np)
    ULL* Wd  = sm + 8192;    // [r][j] stride 513
    ULL* red = sm + 16400;   // [jslg*16 + r][np] stride 17
    ULL* vsm = sm + 18576;   // [r][np] stride 17

    const int tid  = threadIdx.x;
    const int cta  = blockIdx.x;
    const int lane = tid & 31;
    const int wid  = tid >> 5;         // warp id = j-slice id (0..7)

    // ---- stage W_hh (dup'd) once: 16 rows x 512 ----
    for (int i = 0; i < 32; i++) {
        int lin = tid + 256 * i;           // 0..8191
        int r = lin >> 9, j = lin & 511;
        int grow = (r >> 2) * HH + cta * 4 + (r & 3);
        Wd[r * 513 + j] = f2_dup(__ldg(Whh + (size_t)grow * HH + j));
    }
    __syncthreads();

    // GEMM mapping (lane-local within warp)
    const int rowg  = lane & 7;        // 8 row-groups (2 rows each)
    const int npg   = (lane >> 3) & 3; // 4 np-groups (4 pairs each)
    const int rbase = rowg * 2;
    const int np0   = npg * 4;
    const int jb    = wid * 64;        // this warp's j-slice base

    // reduce/gate mapping
    const int rr  = tid >> 4;          // 0..15 gate-row
    const int rnp = tid & 15;          // 0..15 np
    const int rgrow = (rr >> 2) * HH + cta * 4 + (rr & 3);
    const int gu  = tid >> 4;          // gates: tid<64 -> unit 0..3

    float c0 = 0.0f, c1 = 0.0f;

    for (int t = 0; t < TT; t++) {
        // xh prefetch (independent of barrier)
        ULL xh_pair = *(const ULL*)(g_xh + ((size_t)t * GG + rgrow) * NB + 2 * rnp);

        // ---- per-warp acquire poll for h_{t-1} ----
        if (t > 0) {
            if (lane == 0) {
                while (ld_acq(&g_bar[t - 1]) < GRID_B) {}
            }
            __syncwarp();
        }

        // ---- per-warp pipelined fill of own hs slice (2 stages x 32 rows) ----
        const ULL* src = &g_hp[t & 1][0][0] + wid * 1024;
        ULL*       dst = hs + wid * 1024;
        ulonglong2 rA[8], rB[8];
        #pragma unroll
        for (int i = 0; i < 8; i++) rA[i] = ldg_cg2(src + i * 64 + lane * 2);
        #pragma unroll
        for (int i = 0; i < 8; i++) rB[i] = ldg_cg2(src + 512 + i * 64 + lane * 2);
        #pragma unroll
        for (int i = 0; i < 8; i++) *(ulonglong2*)(dst + i * 64 + lane * 2) = rA[i];
        __syncwarp();

        ULL acc[8];
        #pragma unroll
        for (int i = 0; i < 8; i++) acc[i] = 0ULL;

        // ---- GEMM stage 0: rows [jb, jb+32) ----
        {
            const ULL* wr0 = Wd + rbase * 513 + jb;
            const ULL* wr1 = wr0 + 513;
            const ULL* hp  = hs + jb * 16 + np0;
            #pragma unroll 4
            for (int j = 0; j < 32; j++) {
                ULL w0 = wr0[j];
                ULL w1 = wr1[j];
                ulonglong2 ha = *(const ulonglong2*)(hp + j * 16);
                ulonglong2 hb = *(const ulonglong2*)(hp + j * 16 + 2);
                ffma2(acc[0], w0, ha.x); ffma2(acc[1], w0, ha.y);
                ffma2(acc[2], w0, hb.x); ffma2(acc[3], w0, hb.y);
                ffma2(acc[4], w1, ha.x); ffma2(acc[5], w1, ha.y);
                ffma2(acc[6], w1, hb.x); ffma2(acc[7], w1, hb.y);
            }
        }
        // stage-1 STS (data arrived during stage-0 GEMM)
        #pragma unroll
        for (int i = 0; i < 8; i++) *(ulonglong2*)(dst + 512 + i * 64 + lane * 2) = rB[i];
        __syncwarp();

        // ---- GEMM stage 1: rows [jb+32, jb+64) ----
        {
            const ULL* wr0 = Wd + rbase * 513 + jb + 32;
            const ULL* wr1 = wr0 + 513;
            const ULL* hp  = hs + (jb + 32) * 16 + np0;
            #pragma unroll 4
            for (int j = 0; j < 32; j++) {
                ULL w0 = wr0[j];
                ULL w1 = wr1[j];
                ulonglong2 ha = *(const ulonglong2*)(hp + j * 16);
                ulonglong2 hb = *(const ulonglong2*)(hp + j * 16 + 2);
                ffma2(acc[0], w0, ha.x); ffma2(acc[1], w0, ha.y);
                ffma2(acc[2], w0, hb.x); ffma2(acc[3], w0, hb.y);
                ffma2(acc[4], w1, ha.x); ffma2(acc[5], w1, ha.y);
                ffma2(acc[6], w1, hb.x); ffma2(acc[7], w1, hb.y);
            }
        }

        // write partials
        #pragma unroll
        for (int i = 0; i < 2; i++)
            #pragma unroll
            for (int p = 0; p < 4; p++)
                red[(wid * 16 + rbase + i) * 17 + np0 + p] = acc[i * 4 + p];
        __syncthreads();

        // ---- reduce 8 slices + xh -> v ----
        {
            ULL s = red[rr * 17 + rnp];
            #pragma unroll
            for (int sl = 1; sl < 8; sl++) fadd2(s, red[(sl * 16 + rr) * 17 + rnp]);
            fadd2(s, xh_pair);
            vsm[rr * 17 + rnp] = s;
        }
        __syncthreads();

        // ---- gates (64 threads: 4 units x 16 np) ----
        if (tid < 64) {
            float2 vi = f2_unpack(vsm[(0 + gu) * 17 + rnp]);
            float2 vf = f2_unpack(vsm[(4 + gu) * 17 + rnp]);
            float2 vo = f2_unpack(vsm[(8 + gu) * 17 + rnp]);
            float2 vg = f2_unpack(vsm[(12 + gu) * 17 + rnp]);
            float i0 = sig_(vi.x), i1 = sig_(vi.y);
            float f0 = sig_(vf.x), f1 = sig_(vf.y);
            float o0 = sig_(vo.x), o1 = sig_(vo.y);
            float gg0 = tanh_(vg.x), gg1 = tanh_(vg.y);
            c0 = fmaf(f0, c0, i0 * gg0);
            c1 = fmaf(f1, c1, i1 * gg1);
            float h0 = o0 * tanh_(c0);
            float h1 = o1 * tanh_(c1);
            int j = cta * 4 + gu;
            stg_cg64(&g_hp[(t + 1) & 1][j][rnp], f2_pack(h0, h1));
            // order the 64 h-stores before the single release
            asm volatile("bar.sync 1, 64;" ::: "memory");
            if (tid == 0) red_release(&g_bar[t]);
            // epilogue off the critical path
            out[((size_t)(2 * rnp) * TT + t) * HH + j]     = h0;
            out[((size_t)(2 * rnp + 1) * TT + t) * HH + j] = h1;
        }
        // no CTA-wide sync needed here: warps self-gate on g_bar[t] next iter
    }
}

// =====================================================================
extern "C" void kernel_launch(void* const* d_in, const int* in_sizes, int n_in,
                              void* d_out, int out_size) {
    const float* x   = (const float*)d_in[0];
    const float* Wih = (const float*)d_in[1];
    const float* bih = (const float*)d_in[2];
    const float* Whh = (const float*)d_in[3];
    const float* bhh = (const float*)d_in[4];
    float* out = (float*)d_out;

    k_init<<<32, 256>>>();

    dim3 gA(GG / 256, TT);
    k_inproj<<<gA, 256>>>(x, Wih, bih, bhh);

    const int smemB = 18848 * 8;  // 150784 B
    cudaFuncSetAttribute(k_lstm, cudaFuncAttributeMaxDynamicSharedMemorySize, smemB);
    k_lstm<<<GRID_B, 256, smemB>>>(Whh, out);
}